// round 15
// baseline (speedup 1.0000x reference)
#include <cuda_runtime.h>
#include <cuda_fp16.h>
#include <math.h>
#include <stdint.h>

#define BATCH 4
#define SEQ   2048
#define EMB   2048
#define H_Q   16
#define H_KV  4
#define DHEAD 128
#define KVDIM (H_KV*DHEAD)     // 512
#define GQA   (H_Q/H_KV)       // 4

#define XN   (BATCH*SEQ*EMB)
#define KN   (BATCH*SEQ*KVDIM)
#define WQN  (EMB*EMB)
#define WKN  (KVDIM*EMB)

// ---------------- scratch (no allocations allowed) ----------------
__device__ float g_cos[SEQ*64];
__device__ float g_sin[SEQ*64];
__device__ __half g_x16[XN];
__device__ __half g_wqhi[WQN], g_wqlo[WQN];
__device__ __half g_wkhi[WKN], g_wklo[WKN];
__device__ __half g_wvhi[WKN], g_wvlo[WKN];
__device__ __half g_wohi[WQN], g_wolo[WQN];
__device__ __half g_qhi[XN], g_qlo[XN];
__device__ __half g_k16[KN], g_v16[KN];
__device__ __half g_o16[XN];

// ---------------- helpers ----------------
__device__ __forceinline__ uint32_t smem_u32(const void* p) {
    uint32_t a;
    asm("{ .reg .u64 t; cvta.to.shared.u64 t, %1; cvt.u32.u64 %0, t; }" : "=r"(a) : "l"(p));
    return a;
}
__device__ __forceinline__ void cp16(uint32_t dst, const void* src) {
    asm volatile("cp.async.cg.shared.global [%0], [%1], 16;" :: "r"(dst), "l"(src) : "memory");
}
#define CP_COMMIT() asm volatile("cp.async.commit_group;" ::: "memory")
#define CP_WAIT0()  asm volatile("cp.async.wait_group 0;" ::: "memory")
#define CP_WAIT1()  asm volatile("cp.async.wait_group 1;" ::: "memory")

__device__ __forceinline__ void ldm_x4(uint32_t* r, uint32_t addr) {
    asm volatile("ldmatrix.sync.aligned.m8n8.x4.shared.b16 {%0,%1,%2,%3}, [%4];"
                 : "=r"(r[0]), "=r"(r[1]), "=r"(r[2]), "=r"(r[3]) : "r"(addr));
}
__device__ __forceinline__ void ldm_x4_t(uint32_t* r, uint32_t addr) {
    asm volatile("ldmatrix.sync.aligned.m8n8.x4.trans.shared.b16 {%0,%1,%2,%3}, [%4];"
                 : "=r"(r[0]), "=r"(r[1]), "=r"(r[2]), "=r"(r[3]) : "r"(addr));
}
__device__ __forceinline__ void mma16816(float* c, const uint32_t* a, uint32_t b0, uint32_t b1) {
    asm volatile(
        "mma.sync.aligned.m16n8k16.row.col.f32.f16.f16.f32 "
        "{%0,%1,%2,%3}, {%4,%5,%6,%7}, {%8,%9}, {%0,%1,%2,%3};"
        : "+f"(c[0]), "+f"(c[1]), "+f"(c[2]), "+f"(c[3])
        : "r"(a[0]), "r"(a[1]), "r"(a[2]), "r"(a[3]), "r"(b0), "r"(b1));
}
__device__ __forceinline__ uint32_t packh(float lo, float hi) {
    uint32_t r;
    asm("cvt.rn.f16x2.f32 %0, %1, %2;" : "=r"(r) : "f"(hi), "f"(lo));
    return r;
}
__device__ __forceinline__ float hround(float x) {
    return __half2float(__float2half(x));
}

// ---------------- fp32 -> fp16 convert (single) ----------------
__global__ void cvt_f16_kernel(const float* __restrict__ src, __half* __restrict__ dst, int n4) {
    int i = blockIdx.x * blockDim.x + threadIdx.x;
    if (i >= n4) return;
    float4 v = ((const float4*)src)[i];
    uint2 o;
    o.x = packh(v.x, v.y);
    o.y = packh(v.z, v.w);
    ((uint2*)dst)[i] = o;
}

// ---------------- fp32 -> fp16 hi/lo split ----------------
__global__ void split_f16_kernel(const float* __restrict__ src,
                                 __half* __restrict__ hi, __half* __restrict__ lo, int n4) {
    int i = blockIdx.x * blockDim.x + threadIdx.x;
    if (i >= n4) return;
    float4 v = ((const float4*)src)[i];
    float h0 = hround(v.x), h1 = hround(v.y), h2 = hround(v.z), h3 = hround(v.w);
    uint2 hv, lv;
    hv.x = packh(h0, h1);
    hv.y = packh(h2, h3);
    lv.x = packh(v.x - h0, v.y - h1);
    lv.y = packh(v.z - h2, v.w - h3);
    ((uint2*)hi)[i] = hv;
    ((uint2*)lo)[i] = lv;
}

// ---------------- RoPE table ----------------
__global__ void rope_table_kernel(float* ctab, float* stab) {
    int idx = blockIdx.x * blockDim.x + threadIdx.x;
    if (idx >= SEQ * 64) return;
    int pos = idx >> 6;
    int j   = idx & 63;
    float invf = expf(-(float)j * (9.210340371976184f / 64.0f));
    float arg = (float)pos * invf;
    float s, c;
    sincosf(arg, &s, &c);
    ctab[idx] = c;
    stab[idx] = s;
}

// ---------------- in-place RoPE on fp16 hi/lo pairs ----------------
__global__ void rope_hl_kernel(__half* __restrict__ hi, __half* __restrict__ lo,
                               const float* __restrict__ ctab, const float* __restrict__ stab,
                               int nheads, float scale) {
    int idx = blockIdx.x * blockDim.x + threadIdx.x;
    int total = BATCH * SEQ * nheads * 64;
    if (idx >= total) return;
    int j  = idx & 63;
    int tt = idx >> 6;
    int h  = tt % nheads;
    int t2 = tt / nheads;
    int s  = t2 % SEQ;
    int b  = t2 / SEQ;
    float c  = ctab[s * 64 + j];
    float sn = stab[s * 64 + j];
    size_t base = (((size_t)b * SEQ + s) * nheads + h) * DHEAD;
    float x0 = __half2float(hi[base + j])      + __half2float(lo[base + j]);
    float x1 = __half2float(hi[base + 64 + j]) + __half2float(lo[base + 64 + j]);
    float y0 = (x0 * c - x1 * sn) * scale;
    float y1 = (x1 * c + x0 * sn) * scale;
    float h0 = hround(y0), h1 = hround(y1);
    hi[base + j]      = __float2half(y0);
    hi[base + 64 + j] = __float2half(y1);
    lo[base + j]      = __float2half(y0 - h0);
    lo[base + 64 + j] = __float2half(y1 - h1);
}

// ---------------- in-place RoPE on single fp16 ----------------
__global__ void rope_s_kernel(__half* __restrict__ t,
                              const float* __restrict__ ctab, const float* __restrict__ stab,
                              int nheads) {
    int idx = blockIdx.x * blockDim.x + threadIdx.x;
    int total = BATCH * SEQ * nheads * 64;
    if (idx >= total) return;
    int j  = idx & 63;
    int tt = idx >> 6;
    int h  = tt % nheads;
    int t2 = tt / nheads;
    int s  = t2 % SEQ;
    int b  = t2 / SEQ;
    float c  = ctab[s * 64 + j];
    float sn = stab[s * 64 + j];
    size_t base = (((size_t)b * SEQ + s) * nheads + h) * DHEAD;
    float x0 = __half2float(t[base + j]);
    float x1 = __half2float(t[base + 64 + j]);
    t[base + j]      = __float2half(x0 * c - x1 * sn);
    t[base + 64 + j] = __float2half(x1 * c + x0 * sn);
}

// ---------------- warp-MMA GEMM: C = A @ B^T + bias (fp16 2-pass, BK=64) ----------------
// A: single fp16 [M,K]; B: fp16 hi/lo [N,K]. 128x128 tile, BK=64, 8 warps (2m x 4n).
// Per warp: 64m x 32n -> 4 A ldm + 4 B ldm per ka (was 2+8 with 4m x 2n).
// mode 0: C fp32; mode 1: Ch single fp16; mode 2: Chi/Clo fp16 split.
#define TSTRIDE 72
#define TILE_B  (128 * TSTRIDE * 2)      // 18432
#define STAGE_B (3 * TILE_B)             // 55296
#define GEMM_SMEM (2 * STAGE_B)          // 110592

__global__ __launch_bounds__(256, 2)
void gemm_mma_bias(const __half* __restrict__ A16,
                   const __half* __restrict__ Bhi, const __half* __restrict__ Blo,
                   const float* __restrict__ bias, float* __restrict__ C,
                   __half* __restrict__ Ch,
                   __half* __restrict__ Chi, __half* __restrict__ Clo,
                   int mode, int M, int N, int K) {
    extern __shared__ char dsm[];
    const uint32_t sbase = smem_u32(dsm);

    const int tid  = threadIdx.x;
    const int wid  = tid >> 5;
    const int lane = tid & 31;

    const int bm = blockIdx.y * 128;
    const int bn = blockIdx.x * 128;
    const int warp_m = (wid & 1) * 64;     // 2 m-warps of 64 rows
    const int warp_n = (wid >> 1) * 32;    // 4 n-warps of 32 cols

    const __half* srcs[3] = {A16, Bhi, Blo};
    const int rowbase[3] = {bm, bn, bn};

    const int a_r = lane & 15;
    const int a_k = (lane >> 4) * 8;
    const int b_r = ((lane >> 4) << 3) + (lane & 7);
    const int b_k = ((lane >> 3) & 1) * 8;

    float acc[4][4][4];
#pragma unroll
    for (int mi = 0; mi < 4; mi++)
#pragma unroll
        for (int ni = 0; ni < 4; ni++)
#pragma unroll
            for (int j = 0; j < 4; j++) acc[mi][ni][j] = 0.f;

    const int NC = K >> 6;   // 64-wide chunks

#pragma unroll
    for (int t = 0; t < 3; t++) {
#pragma unroll
        for (int s = 0; s < 4; s++) {
            int seg = tid + s * 256;          // 0..1023
            int row = seg >> 3;
            int qq  = seg & 7;
            const __half* g = srcs[t] + (size_t)(rowbase[t] + row) * K + qq * 8;
            cp16(sbase + t * TILE_B + (uint32_t)(row * TSTRIDE + qq * 8) * 2, g);
        }
    }
    CP_COMMIT();

    for (int c = 0; c < NC; c++) {
        CP_WAIT0();
        __syncthreads();

        if (c + 1 < NC) {
            const uint32_t stg = sbase + ((c + 1) & 1) * STAGE_B;
            const int kt = (c + 1) << 6;
#pragma unroll
            for (int t = 0; t < 3; t++) {
#pragma unroll
                for (int s = 0; s < 4; s++) {
                    int seg = tid + s * 256;
                    int row = seg >> 3;
                    int qq  = seg & 7;
                    const __half* g = srcs[t] + (size_t)(rowbase[t] + row) * K + kt + qq * 8;
                    cp16(stg + t * TILE_B + (uint32_t)(row * TSTRIDE + qq * 8) * 2, g);
                }
            }
            CP_COMMIT();
        }

        const uint32_t stage = sbase + (c & 1) * STAGE_B;
#pragma unroll
        for (int ka = 0; ka < 64; ka += 16) {
            uint32_t ah[4][4];
#pragma unroll
            for (int mi = 0; mi < 4; mi++) {
                uint32_t ro = (uint32_t)((warp_m + mi * 16 + a_r) * TSTRIDE + ka + a_k) * 2;
                ldm_x4(ah[mi], stage + 0 * TILE_B + ro);
            }
#pragma unroll
            for (int nj = 0; nj < 2; nj++) {
                uint32_t ro = (uint32_t)((warp_n + nj * 16 + b_r) * TSTRIDE + ka + b_k) * 2;
                uint32_t bh[4], bl[4];
                ldm_x4(bh, stage + 1 * TILE_B + ro);
                ldm_x4(bl, stage + 2 * TILE_B + ro);
#pragma unroll
                for (int mi = 0; mi < 4; mi++)
#pragma unroll
                    for (int half = 0; half < 2; half++) {
                        const int ni = nj * 2 + half;
                        const int s  = half * 2;
                        mma16816(acc[mi][ni], ah[mi], bh[s], bh[s + 1]);
                        mma16816(acc[mi][ni], ah[mi], bl[s], bl[s + 1]);
                    }
            }
        }
        __syncthreads();
    }

    const int quad = lane >> 2;
    const int tcol = lane & 3;
#pragma unroll
    for (int mi = 0; mi < 4; mi++)
#pragma unroll
        for (int ni = 0; ni < 4; ni++) {
            const int m0 = bm + warp_m + mi * 16 + quad;
            const int n0 = bn + warp_n + ni * 8 + tcol * 2;
            const float b0 = bias[n0], b1 = bias[n0 + 1];
            float c00 = acc[mi][ni][0] + b0, c01 = acc[mi][ni][1] + b1;
            float c10 = acc[mi][ni][2] + b0, c11 = acc[mi][ni][3] + b1;
            size_t i0 = (size_t)m0 * N + n0;
            size_t i1 = (size_t)(m0 + 8) * N + n0;
            if (mode == 0) {
                *(float2*)&C[i0] = make_float2(c00, c01);
                *(float2*)&C[i1] = make_float2(c10, c11);
            } else if (mode == 1) {
                *(uint32_t*)&Ch[i0] = packh(c00, c01);
                *(uint32_t*)&Ch[i1] = packh(c10, c11);
            } else {
                *(uint32_t*)&Chi[i0] = packh(c00, c01);
                *(uint32_t*)&Chi[i1] = packh(c10, c11);
                *(uint32_t*)&Clo[i0] = packh(c00 - hround(c00), c01 - hround(c01));
                *(uint32_t*)&Clo[i1] = packh(c10 - hround(c10), c11 - hround(c11));
            }
        }
}

// ---------------- tensor-core flash attention (fp16 2-pass, double-buffered K/V) ----------------
#define KSTR 136
#define FL_TILE  (64 * KSTR * 2)     // 17408
#define FL_STAGE (2 * FL_TILE)       // 34816
#define FL_SMEM  (2 * FL_STAGE)      // 69632

__global__ __launch_bounds__(128, 2)
void flash_mma_kernel(const __half* __restrict__ Qhi, const __half* __restrict__ Qlo,
                      const __half* __restrict__ K16, const __half* __restrict__ V16,
                      __half* __restrict__ O16) {
    extern __shared__ char sm2[];
    const uint32_t sb = smem_u32(sm2);

    const int qt  = gridDim.x - 1 - blockIdx.x;
    const int bh  = blockIdx.y;
    const int b   = bh >> 4;
    const int h   = bh & 15;
    const int kvh = h >> 2;
    const int q0  = qt * 64;
    const int tid = threadIdx.x;
    const int wid = tid >> 5;
    const int lane = tid & 31;
    const int quad = lane >> 2;
    const int tcol = lane & 3;

#pragma unroll
    for (int s = 0; s < 8; s++) {
        int seg = tid + s * 128;
        int r   = seg >> 4;
        int cg  = seg & 15;
        size_t gofs = (((size_t)b * SEQ + q0 + r) * H_Q + h) * DHEAD + cg * 8;
        uint32_t so = (uint32_t)(r * KSTR + cg * 8) * 2;
        cp16(sb + so, Qhi + gofs);
        cp16(sb + FL_TILE + so, Qlo + gofs);
    }
    CP_COMMIT();
    CP_WAIT0();
    __syncthreads();

    uint32_t qh[8][4], ql[8][4];
    {
        const int a_r = lane & 15;
        const int a_k = (lane >> 4) * 8;
#pragma unroll
        for (int ka = 0; ka < 8; ka++) {
            uint32_t ro = (uint32_t)((wid * 16 + a_r) * KSTR + ka * 16 + a_k) * 2;
            ldm_x4(qh[ka], sb + ro);
            ldm_x4(ql[ka], sb + FL_TILE + ro);
        }
    }
    __syncthreads();

    float o_acc[16][4];
#pragma unroll
    for (int g = 0; g < 16; g++)
#pragma unroll
        for (int j = 0; j < 4; j++) o_acc[g][j] = 0.f;

    float m0 = -1e30f, m1 = -1e30f, l0 = 0.f, l1 = 0.f;

    const int b_r = ((lane >> 4) << 3) + (lane & 7);
    const int b_k = ((lane >> 3) & 1) * 8;
    const int v_kk = (lane & 7) + ((lane >> 3) & 1) * 8;
    const int v_d  = ((lane >> 4) & 1) * 8;

#pragma unroll
    for (int s = 0; s < 8; s++) {
        int seg = tid + s * 128;
        int r   = seg >> 4;
        int cg  = seg & 15;
        size_t gofs = (((size_t)b * SEQ + r) * H_KV + kvh) * DHEAD + cg * 8;
        uint32_t so = (uint32_t)(r * KSTR + cg * 8) * 2;
        cp16(sb + so, K16 + gofs);
        cp16(sb + FL_TILE + so, V16 + gofs);
    }
    CP_COMMIT();

    for (int kt = 0; kt <= qt; kt++) {
        if (kt + 1 <= qt) {
            const uint32_t stg = sb + ((kt + 1) & 1) * FL_STAGE;
            const int k0n = (kt + 1) * 64;
#pragma unroll
            for (int s = 0; s < 8; s++) {
                int seg = tid + s * 128;
                int r   = seg >> 4;
                int cg  = seg & 15;
                size_t gofs = (((size_t)b * SEQ + k0n + r) * H_KV + kvh) * DHEAD + cg * 8;
                uint32_t so = (uint32_t)(r * KSTR + cg * 8) * 2;
                cp16(stg + so, K16 + gofs);
                cp16(stg + FL_TILE + so, V16 + gofs);
            }
        }
        CP_COMMIT();
        CP_WAIT1();
        __syncthreads();

        const uint32_t st = sb + (kt & 1) * FL_STAGE;

        float sc[8][4];
#pragma unroll
        for (int ni = 0; ni < 8; ni++)
#pragma unroll
            for (int j = 0; j < 4; j++) sc[ni][j] = 0.f;

#pragma unroll
        for (int ka = 0; ka < 8; ka++) {
#pragma unroll
            for (int nj = 0; nj < 4; nj++) {
                uint32_t ro = (uint32_t)((nj * 16 + b_r) * KSTR + ka * 16 + b_k) * 2;
                uint32_t kk[4];
                ldm_x4(kk, st + ro);
#pragma unroll
                for (int half = 0; half < 2; half++) {
                    const int ni = nj * 2 + half;
                    const int s2 = half * 2;
                    mma16816(sc[ni], qh[ka], kk[s2], kk[s2 + 1]);
                    mma16816(sc[ni], ql[ka], kk[s2], kk[s2 + 1]);
                }
            }
        }

        if (kt == qt) {
            const int row0 = wid * 16 + quad;
#pragma unroll
            for (int ni = 0; ni < 8; ni++) {
                const int c0 = ni * 8 + 2 * tcol;
                if (c0 > row0)     sc[ni][0] = -1e30f;
                if (c0 + 1 > row0) sc[ni][1] = -1e30f;
                if (c0 > row0 + 8)     sc[ni][2] = -1e30f;
                if (c0 + 1 > row0 + 8) sc[ni][3] = -1e30f;
            }
        }

        float mx0 = -1e30f, mx1 = -1e30f;
#pragma unroll
        for (int ni = 0; ni < 8; ni++) {
            mx0 = fmaxf(mx0, fmaxf(sc[ni][0], sc[ni][1]));
            mx1 = fmaxf(mx1, fmaxf(sc[ni][2], sc[ni][3]));
        }
        mx0 = fmaxf(mx0, __shfl_xor_sync(0xffffffffu, mx0, 1));
        mx0 = fmaxf(mx0, __shfl_xor_sync(0xffffffffu, mx0, 2));
        mx1 = fmaxf(mx1, __shfl_xor_sync(0xffffffffu, mx1, 1));
        mx1 = fmaxf(mx1, __shfl_xor_sync(0xffffffffu, mx1, 2));

        const float nm0 = fmaxf(m0, mx0);
        const float nm1 = fmaxf(m1, mx1);
        const float rs0 = __expf(m0 - nm0);
        const float rs1 = __expf(m1 - nm1);
        m0 = nm0; m1 = nm1;

        float ps0 = 0.f, ps1 = 0.f;
#pragma unroll
        for (int ni = 0; ni < 8; ni++) {
            sc[ni][0] = __expf(sc[ni][0] - nm0);
            sc[ni][1] = __expf(sc[ni][1] - nm0);
            sc[ni][2] = __expf(sc[ni][2] - nm1);
            sc[ni][3] = __expf(sc[ni][3] - nm1);
            ps0 += sc[ni][0] + sc[ni][1];
            ps1 += sc[ni][2] + sc[ni][3];
        }
        ps0 += __shfl_xor_sync(0xffffffffu, ps0, 1);
        ps0 += __shfl_xor_sync(0xffffffffu, ps0, 2);
        ps1 += __shfl_xor_sync(0xffffffffu, ps1, 1);
        ps1 += __shfl_xor_sync(0xffffffffu, ps1, 2);
        l0 = l0 * rs0 + ps0;
        l1 = l1 * rs1 + ps1;

#pragma unroll
        for (int g = 0; g < 16; g++) {
            o_acc[g][0] *= rs0; o_acc[g][1] *= rs0;
            o_acc[g][2] *= rs1; o_acc[g][3] *= rs1;
        }

#pragma unroll
        for (int t = 0; t < 4; t++) {
            float p00 = sc[2*t][0],   p01 = sc[2*t][1],   p02 = sc[2*t][2],   p03 = sc[2*t][3];
            float p10 = sc[2*t+1][0], p11 = sc[2*t+1][1], p12 = sc[2*t+1][2], p13 = sc[2*t+1][3];
            uint32_t aph[4], apl[4];
            aph[0] = packh(p00, p01);
            aph[1] = packh(p02, p03);
            aph[2] = packh(p10, p11);
            aph[3] = packh(p12, p13);
            apl[0] = packh(p00 - hround(p00), p01 - hround(p01));
            apl[1] = packh(p02 - hround(p02), p03 - hround(p03));
            apl[2] = packh(p10 - hround(p10), p11 - hround(p11));
            apl[3] = packh(p12 - hround(p12), p13 - hround(p13));

            const uint32_t vbase = st + FL_TILE + (uint32_t)((t * 16 + v_kk) * KSTR + v_d) * 2;
#pragma unroll
            for (int g = 0; g < 8; g++) {
                uint32_t vv[4];
                ldm_x4_t(vv, vbase + (uint32_t)(g * 16) * 2);
                mma16816(o_acc[g*2],   aph, vv[0], vv[1]);
                mma16816(o_acc[g*2+1], aph, vv[2], vv[3]);
                mma16816(o_acc[g*2],   apl, vv[0], vv[1]);
                mma16816(o_acc[g*2+1], apl, vv[2], vv[3]);
            }
        }
        __syncthreads();
    }

    const float inv0 = 1.f / l0;
    const float inv1 = 1.f / l1;
    const int row0 = q0 + wid * 16 + quad;
#pragma unroll
    for (int g = 0; g < 16; g++) {
        const int d = g * 8 + 2 * tcol;
        float a0 = o_acc[g][0] * inv0, a1 = o_acc[g][1] * inv0;
        float a2 = o_acc[g][2] * inv1, a3 = o_acc[g][3] * inv1;
        size_t i0 = (((size_t)b * SEQ + row0) * H_Q + h) * DHEAD + d;
        size_t i1 = (((size_t)b * SEQ + row0 + 8) * H_Q + h) * DHEAD + d;
        *(uint32_t*)&O16[i0] = packh(a0, a1);
        *(uint32_t*)&O16[i1] = packh(a2, a3);
    }
}

// ---------------- launch ----------------
extern "C" void kernel_launch(void* const* d_in, const int* in_sizes, int n_in,
                              void* d_out, int out_size) {
    const float* x  = (const float*)d_in[0];
    const float* wq = (const float*)d_in[1];
    const float* bq = (const float*)d_in[2];
    const float* wk = (const float*)d_in[3];
    const float* bk = (const float*)d_in[4];
    const float* wv = (const float*)d_in[5];
    const float* bv = (const float*)d_in[6];
    const float* wo = (const float*)d_in[7];
    const float* bo = (const float*)d_in[8];
    float* out = (float*)d_out;

    float *ctab, *stab;
    cudaGetSymbolAddress((void**)&ctab, g_cos);
    cudaGetSymbolAddress((void**)&stab, g_sin);

    __half *x16, *wqhi, *wqlo, *wkhi, *wklo, *wvhi, *wvlo, *wohi, *wolo;
    __half *qhi, *qlo, *k16, *v16, *o16;
    cudaGetSymbolAddress((void**)&x16, g_x16);
    cudaGetSymbolAddress((void**)&wqhi, g_wqhi); cudaGetSymbolAddress((void**)&wqlo, g_wqlo);
    cudaGetSymbolAddress((void**)&wkhi, g_wkhi); cudaGetSymbolAddress((void**)&wklo, g_wklo);
    cudaGetSymbolAddress((void**)&wvhi, g_wvhi); cudaGetSymbolAddress((void**)&wvlo, g_wvlo);
    cudaGetSymbolAddress((void**)&wohi, g_wohi); cudaGetSymbolAddress((void**)&wolo, g_wolo);
    cudaGetSymbolAddress((void**)&qhi, g_qhi);   cudaGetSymbolAddress((void**)&qlo, g_qlo);
    cudaGetSymbolAddress((void**)&k16, g_k16);   cudaGetSymbolAddress((void**)&v16, g_v16);
    cudaGetSymbolAddress((void**)&o16, g_o16);

    const int M = BATCH * SEQ;   // 8192

    cudaFuncSetAttribute(gemm_mma_bias, cudaFuncAttributeMaxDynamicSharedMemorySize, GEMM_SMEM);
    cudaFuncSetAttribute(flash_mma_kernel, cudaFuncAttributeMaxDynamicSharedMemorySize, FL_SMEM);

    rope_table_kernel<<<(SEQ * 64 + 255) / 256, 256>>>(ctab, stab);
    cvt_f16_kernel<<<(XN / 4 + 255) / 256, 256>>>(x, x16, XN / 4);
    split_f16_kernel<<<(WQN / 4 + 255) / 256, 256>>>(wq, wqhi, wqlo, WQN / 4);
    split_f16_kernel<<<(WKN / 4 + 255) / 256, 256>>>(wk, wkhi, wklo, WKN / 4);
    split_f16_kernel<<<(WKN / 4 + 255) / 256, 256>>>(wv, wvhi, wvlo, WKN / 4);
    split_f16_kernel<<<(WQN / 4 + 255) / 256, 256>>>(wo, wohi, wolo, WQN / 4);

    // projections (128x128 tiles, 2 CTAs/SM)
    gemm_mma_bias<<<dim3(EMB / 128, M / 128), 256, GEMM_SMEM>>>(
        x16, wqhi, wqlo, bq, (float*)0, (__half*)0, qhi, qlo, 2, M, EMB, EMB);
    gemm_mma_bias<<<dim3(KVDIM / 128, M / 128), 256, GEMM_SMEM>>>(
        x16, wkhi, wklo, bk, (float*)0, k16, (__half*)0, (__half*)0, 1, M, KVDIM, EMB);
    gemm_mma_bias<<<dim3(KVDIM / 128, M / 128), 256, GEMM_SMEM>>>(
        x16, wvhi, wvlo, bv, (float*)0, v16, (__half*)0, (__half*)0, 1, M, KVDIM, EMB);

    // RoPE
    {
        const float qscale = 0.08838834764831845f;   // 1/sqrt(128)
        int tq = BATCH * SEQ * H_Q * 64;
        rope_hl_kernel<<<(tq + 255) / 256, 256>>>(qhi, qlo, ctab, stab, H_Q, qscale);
        int tk = BATCH * SEQ * H_KV * 64;
        rope_s_kernel<<<(tk + 255) / 256, 256>>>(k16, ctab, stab, H_KV);
    }

    // flash attention -> o16
    flash_mma_kernel<<<dim3(SEQ / 64, BATCH * H_Q), 128, FL_SMEM>>>(
        qhi, qlo, k16, v16, o16);

    // output projection (fp32 out)
    gemm_mma_bias<<<dim3(EMB / 128, M / 128), 256, GEMM_SMEM>>>(
        o16, wohi, wolo, bo, out, (__half*)0, (__half*)0, (__half*)0, 0, M, EMB, EMB);
}

// round 16
// speedup vs baseline: 1.0058x; 1.0058x over previous
#include <cuda_runtime.h>
#include <cuda_fp16.h>
#include <math.h>
#include <stdint.h>

#define BATCH 4
#define SEQ   2048
#define EMB   2048
#define H_Q   16
#define H_KV  4
#define DHEAD 128
#define KVDIM (H_KV*DHEAD)     // 512
#define GQA   (H_Q/H_KV)       // 4

#define XN   (BATCH*SEQ*EMB)
#define KN   (BATCH*SEQ*KVDIM)
#define WQN  (EMB*EMB)
#define WKN  (KVDIM*EMB)

// ---------------- scratch (no allocations allowed) ----------------
__device__ float g_cos[SEQ*64];
__device__ float g_sin[SEQ*64];
__device__ __half g_x16[XN];
__device__ __half g_wqhi[WQN], g_wqlo[WQN];
__device__ __half g_wkhi[WKN], g_wklo[WKN];
__device__ __half g_wvhi[WKN], g_wvlo[WKN];
__device__ __half g_wohi[WQN], g_wolo[WQN];
__device__ __half g_qhi[XN], g_qlo[XN];
__device__ __half g_k16[KN], g_v16[KN];
__device__ __half g_o16[XN];

// ---------------- helpers ----------------
__device__ __forceinline__ uint32_t smem_u32(const void* p) {
    uint32_t a;
    asm("{ .reg .u64 t; cvta.to.shared.u64 t, %1; cvt.u32.u64 %0, t; }" : "=r"(a) : "l"(p));
    return a;
}
__device__ __forceinline__ void cp16(uint32_t dst, const void* src) {
    asm volatile("cp.async.cg.shared.global [%0], [%1], 16;" :: "r"(dst), "l"(src) : "memory");
}
#define CP_COMMIT() asm volatile("cp.async.commit_group;" ::: "memory")
#define CP_WAIT0()  asm volatile("cp.async.wait_group 0;" ::: "memory")
#define CP_WAIT1()  asm volatile("cp.async.wait_group 1;" ::: "memory")

__device__ __forceinline__ void ldm_x4(uint32_t* r, uint32_t addr) {
    asm volatile("ldmatrix.sync.aligned.m8n8.x4.shared.b16 {%0,%1,%2,%3}, [%4];"
                 : "=r"(r[0]), "=r"(r[1]), "=r"(r[2]), "=r"(r[3]) : "r"(addr));
}
__device__ __forceinline__ void ldm_x4_t(uint32_t* r, uint32_t addr) {
    asm volatile("ldmatrix.sync.aligned.m8n8.x4.trans.shared.b16 {%0,%1,%2,%3}, [%4];"
                 : "=r"(r[0]), "=r"(r[1]), "=r"(r[2]), "=r"(r[3]) : "r"(addr));
}
__device__ __forceinline__ void mma16816(float* c, const uint32_t* a, uint32_t b0, uint32_t b1) {
    asm volatile(
        "mma.sync.aligned.m16n8k16.row.col.f32.f16.f16.f32 "
        "{%0,%1,%2,%3}, {%4,%5,%6,%7}, {%8,%9}, {%0,%1,%2,%3};"
        : "+f"(c[0]), "+f"(c[1]), "+f"(c[2]), "+f"(c[3])
        : "r"(a[0]), "r"(a[1]), "r"(a[2]), "r"(a[3]), "r"(b0), "r"(b1));
}
__device__ __forceinline__ uint32_t packh(float lo, float hi) {
    uint32_t r;
    asm("cvt.rn.f16x2.f32 %0, %1, %2;" : "=r"(r) : "f"(hi), "f"(lo));
    return r;
}
__device__ __forceinline__ float hround(float x) {
    return __half2float(__float2half(x));
}

// ---------------- fp32 -> fp16 convert (single) ----------------
__global__ void cvt_f16_kernel(const float* __restrict__ src, __half* __restrict__ dst, int n4) {
    int i = blockIdx.x * blockDim.x + threadIdx.x;
    if (i >= n4) return;
    float4 v = ((const float4*)src)[i];
    uint2 o;
    o.x = packh(v.x, v.y);
    o.y = packh(v.z, v.w);
    ((uint2*)dst)[i] = o;
}

// ---------------- fp32 -> fp16 hi/lo split ----------------
__global__ void split_f16_kernel(const float* __restrict__ src,
                                 __half* __restrict__ hi, __half* __restrict__ lo, int n4) {
    int i = blockIdx.x * blockDim.x + threadIdx.x;
    if (i >= n4) return;
    float4 v = ((const float4*)src)[i];
    float h0 = hround(v.x), h1 = hround(v.y), h2 = hround(v.z), h3 = hround(v.w);
    uint2 hv, lv;
    hv.x = packh(h0, h1);
    hv.y = packh(h2, h3);
    lv.x = packh(v.x - h0, v.y - h1);
    lv.y = packh(v.z - h2, v.w - h3);
    ((uint2*)hi)[i] = hv;
    ((uint2*)lo)[i] = lv;
}

// ---------------- RoPE table ----------------
__global__ void rope_table_kernel(float* ctab, float* stab) {
    int idx = blockIdx.x * blockDim.x + threadIdx.x;
    if (idx >= SEQ * 64) return;
    int pos = idx >> 6;
    int j   = idx & 63;
    float invf = expf(-(float)j * (9.210340371976184f / 64.0f));
    float arg = (float)pos * invf;
    float s, c;
    sincosf(arg, &s, &c);
    ctab[idx] = c;
    stab[idx] = s;
}

// ---------------- in-place RoPE on fp16 hi/lo pairs ----------------
__global__ void rope_hl_kernel(__half* __restrict__ hi, __half* __restrict__ lo,
                               const float* __restrict__ ctab, const float* __restrict__ stab,
                               int nheads, float scale) {
    int idx = blockIdx.x * blockDim.x + threadIdx.x;
    int total = BATCH * SEQ * nheads * 64;
    if (idx >= total) return;
    int j  = idx & 63;
    int tt = idx >> 6;
    int h  = tt % nheads;
    int t2 = tt / nheads;
    int s  = t2 % SEQ;
    int b  = t2 / SEQ;
    float c  = ctab[s * 64 + j];
    float sn = stab[s * 64 + j];
    size_t base = (((size_t)b * SEQ + s) * nheads + h) * DHEAD;
    float x0 = __half2float(hi[base + j])      + __half2float(lo[base + j]);
    float x1 = __half2float(hi[base + 64 + j]) + __half2float(lo[base + 64 + j]);
    float y0 = (x0 * c - x1 * sn) * scale;
    float y1 = (x1 * c + x0 * sn) * scale;
    float h0 = hround(y0), h1 = hround(y1);
    hi[base + j]      = __float2half(y0);
    hi[base + 64 + j] = __float2half(y1);
    lo[base + j]      = __float2half(y0 - h0);
    lo[base + 64 + j] = __float2half(y1 - h1);
}

// ---------------- in-place RoPE on single fp16 ----------------
__global__ void rope_s_kernel(__half* __restrict__ t,
                              const float* __restrict__ ctab, const float* __restrict__ stab,
                              int nheads) {
    int idx = blockIdx.x * blockDim.x + threadIdx.x;
    int total = BATCH * SEQ * nheads * 64;
    if (idx >= total) return;
    int j  = idx & 63;
    int tt = idx >> 6;
    int h  = tt % nheads;
    int t2 = tt / nheads;
    int s  = t2 % SEQ;
    int b  = t2 / SEQ;
    float c  = ctab[s * 64 + j];
    float sn = stab[s * 64 + j];
    size_t base = (((size_t)b * SEQ + s) * nheads + h) * DHEAD;
    float x0 = __half2float(t[base + j]);
    float x1 = __half2float(t[base + 64 + j]);
    t[base + j]      = __float2half(x0 * c - x1 * sn);
    t[base + 64 + j] = __float2half(x1 * c + x0 * sn);
}

// ---------------- warp-MMA GEMM: C = A @ B^T + bias (fp16 2-pass, BK=64) ----------------
// A: single fp16 [M,K]; B: fp16 hi/lo [N,K]. 128x128 tile, BK=64, 8 warps (2m x 4n).
// Per warp: 64m x 32n -> 4 A ldm + 4 B ldm per ka (was 2+8 with 4m x 2n).
// mode 0: C fp32; mode 1: Ch single fp16; mode 2: Chi/Clo fp16 split.
#define TSTRIDE 72
#define TILE_B  (128 * TSTRIDE * 2)      // 18432
#define STAGE_B (3 * TILE_B)             // 55296
#define GEMM_SMEM (2 * STAGE_B)          // 110592

__global__ __launch_bounds__(256, 2)
void gemm_mma_bias(const __half* __restrict__ A16,
                   const __half* __restrict__ Bhi, const __half* __restrict__ Blo,
                   const float* __restrict__ bias, float* __restrict__ C,
                   __half* __restrict__ Ch,
                   __half* __restrict__ Chi, __half* __restrict__ Clo,
                   int mode, int M, int N, int K) {
    extern __shared__ char dsm[];
    const uint32_t sbase = smem_u32(dsm);

    const int tid  = threadIdx.x;
    const int wid  = tid >> 5;
    const int lane = tid & 31;

    const int bm = blockIdx.y * 128;
    const int bn = blockIdx.x * 128;
    const int warp_m = (wid & 1) * 64;     // 2 m-warps of 64 rows
    const int warp_n = (wid >> 1) * 32;    // 4 n-warps of 32 cols

    const __half* srcs[3] = {A16, Bhi, Blo};
    const int rowbase[3] = {bm, bn, bn};

    const int a_r = lane & 15;
    const int a_k = (lane >> 4) * 8;
    const int b_r = ((lane >> 4) << 3) + (lane & 7);
    const int b_k = ((lane >> 3) & 1) * 8;

    float acc[4][4][4];
#pragma unroll
    for (int mi = 0; mi < 4; mi++)
#pragma unroll
        for (int ni = 0; ni < 4; ni++)
#pragma unroll
            for (int j = 0; j < 4; j++) acc[mi][ni][j] = 0.f;

    const int NC = K >> 6;   // 64-wide chunks

#pragma unroll
    for (int t = 0; t < 3; t++) {
#pragma unroll
        for (int s = 0; s < 4; s++) {
            int seg = tid + s * 256;          // 0..1023
            int row = seg >> 3;
            int qq  = seg & 7;
            const __half* g = srcs[t] + (size_t)(rowbase[t] + row) * K + qq * 8;
            cp16(sbase + t * TILE_B + (uint32_t)(row * TSTRIDE + qq * 8) * 2, g);
        }
    }
    CP_COMMIT();

    for (int c = 0; c < NC; c++) {
        CP_WAIT0();
        __syncthreads();

        if (c + 1 < NC) {
            const uint32_t stg = sbase + ((c + 1) & 1) * STAGE_B;
            const int kt = (c + 1) << 6;
#pragma unroll
            for (int t = 0; t < 3; t++) {
#pragma unroll
                for (int s = 0; s < 4; s++) {
                    int seg = tid + s * 256;
                    int row = seg >> 3;
                    int qq  = seg & 7;
                    const __half* g = srcs[t] + (size_t)(rowbase[t] + row) * K + kt + qq * 8;
                    cp16(stg + t * TILE_B + (uint32_t)(row * TSTRIDE + qq * 8) * 2, g);
                }
            }
            CP_COMMIT();
        }

        const uint32_t stage = sbase + (c & 1) * STAGE_B;
#pragma unroll
        for (int ka = 0; ka < 64; ka += 16) {
            uint32_t ah[4][4];
#pragma unroll
            for (int mi = 0; mi < 4; mi++) {
                uint32_t ro = (uint32_t)((warp_m + mi * 16 + a_r) * TSTRIDE + ka + a_k) * 2;
                ldm_x4(ah[mi], stage + 0 * TILE_B + ro);
            }
#pragma unroll
            for (int nj = 0; nj < 2; nj++) {
                uint32_t ro = (uint32_t)((warp_n + nj * 16 + b_r) * TSTRIDE + ka + b_k) * 2;
                uint32_t bh[4], bl[4];
                ldm_x4(bh, stage + 1 * TILE_B + ro);
                ldm_x4(bl, stage + 2 * TILE_B + ro);
#pragma unroll
                for (int mi = 0; mi < 4; mi++)
#pragma unroll
                    for (int half = 0; half < 2; half++) {
                        const int ni = nj * 2 + half;
                        const int s  = half * 2;
                        mma16816(acc[mi][ni], ah[mi], bh[s], bh[s + 1]);
                        mma16816(acc[mi][ni], ah[mi], bl[s], bl[s + 1]);
                    }
            }
        }
        __syncthreads();
    }

    const int quad = lane >> 2;
    const int tcol = lane & 3;
#pragma unroll
    for (int mi = 0; mi < 4; mi++)
#pragma unroll
        for (int ni = 0; ni < 4; ni++) {
            const int m0 = bm + warp_m + mi * 16 + quad;
            const int n0 = bn + warp_n + ni * 8 + tcol * 2;
            const float b0 = bias[n0], b1 = bias[n0 + 1];
            float c00 = acc[mi][ni][0] + b0, c01 = acc[mi][ni][1] + b1;
            float c10 = acc[mi][ni][2] + b0, c11 = acc[mi][ni][3] + b1;
            size_t i0 = (size_t)m0 * N + n0;
            size_t i1 = (size_t)(m0 + 8) * N + n0;
            if (mode == 0) {
                *(float2*)&C[i0] = make_float2(c00, c01);
                *(float2*)&C[i1] = make_float2(c10, c11);
            } else if (mode == 1) {
                *(uint32_t*)&Ch[i0] = packh(c00, c01);
                *(uint32_t*)&Ch[i1] = packh(c10, c11);
            } else {
                *(uint32_t*)&Chi[i0] = packh(c00, c01);
                *(uint32_t*)&Chi[i1] = packh(c10, c11);
                *(uint32_t*)&Clo[i0] = packh(c00 - hround(c00), c01 - hround(c01));
                *(uint32_t*)&Clo[i1] = packh(c10 - hround(c10), c11 - hround(c11));
            }
        }
}

// ---------------- tensor-core flash attention (fp16 2-pass, double-buffered K/V) ----------------
#define KSTR 136
#define FL_TILE  (64 * KSTR * 2)     // 17408
#define FL_STAGE (2 * FL_TILE)       // 34816
#define FL_SMEM  (2 * FL_STAGE)      // 69632

__global__ __launch_bounds__(128, 2)
void flash_mma_kernel(const __half* __restrict__ Qhi, const __half* __restrict__ Qlo,
                      const __half* __restrict__ K16, const __half* __restrict__ V16,
                      __half* __restrict__ O16) {
    extern __shared__ char sm2[];
    const uint32_t sb = smem_u32(sm2);

    const int qt  = gridDim.x - 1 - blockIdx.x;
    const int bh  = blockIdx.y;
    const int b   = bh >> 4;
    const int h   = bh & 15;
    const int kvh = h >> 2;
    const int q0  = qt * 64;
    const int tid = threadIdx.x;
    const int wid = tid >> 5;
    const int lane = tid & 31;
    const int quad = lane >> 2;
    const int tcol = lane & 3;

#pragma unroll
    for (int s = 0; s < 8; s++) {
        int seg = tid + s * 128;
        int r   = seg >> 4;
        int cg  = seg & 15;
        size_t gofs = (((size_t)b * SEQ + q0 + r) * H_Q + h) * DHEAD + cg * 8;
        uint32_t so = (uint32_t)(r * KSTR + cg * 8) * 2;
        cp16(sb + so, Qhi + gofs);
        cp16(sb + FL_TILE + so, Qlo + gofs);
    }
    CP_COMMIT();
    CP_WAIT0();
    __syncthreads();

    uint32_t qh[8][4], ql[8][4];
    {
        const int a_r = lane & 15;
        const int a_k = (lane >> 4) * 8;
#pragma unroll
        for (int ka = 0; ka < 8; ka++) {
            uint32_t ro = (uint32_t)((wid * 16 + a_r) * KSTR + ka * 16 + a_k) * 2;
            ldm_x4(qh[ka], sb + ro);
            ldm_x4(ql[ka], sb + FL_TILE + ro);
        }
    }
    __syncthreads();

    float o_acc[16][4];
#pragma unroll
    for (int g = 0; g < 16; g++)
#pragma unroll
        for (int j = 0; j < 4; j++) o_acc[g][j] = 0.f;

    float m0 = -1e30f, m1 = -1e30f, l0 = 0.f, l1 = 0.f;

    const int b_r = ((lane >> 4) << 3) + (lane & 7);
    const int b_k = ((lane >> 3) & 1) * 8;
    const int v_kk = (lane & 7) + ((lane >> 3) & 1) * 8;
    const int v_d  = ((lane >> 4) & 1) * 8;

#pragma unroll
    for (int s = 0; s < 8; s++) {
        int seg = tid + s * 128;
        int r   = seg >> 4;
        int cg  = seg & 15;
        size_t gofs = (((size_t)b * SEQ + r) * H_KV + kvh) * DHEAD + cg * 8;
        uint32_t so = (uint32_t)(r * KSTR + cg * 8) * 2;
        cp16(sb + so, K16 + gofs);
        cp16(sb + FL_TILE + so, V16 + gofs);
    }
    CP_COMMIT();

    for (int kt = 0; kt <= qt; kt++) {
        if (kt + 1 <= qt) {
            const uint32_t stg = sb + ((kt + 1) & 1) * FL_STAGE;
            const int k0n = (kt + 1) * 64;
#pragma unroll
            for (int s = 0; s < 8; s++) {
                int seg = tid + s * 128;
                int r   = seg >> 4;
                int cg  = seg & 15;
                size_t gofs = (((size_t)b * SEQ + k0n + r) * H_KV + kvh) * DHEAD + cg * 8;
                uint32_t so = (uint32_t)(r * KSTR + cg * 8) * 2;
                cp16(stg + so, K16 + gofs);
                cp16(stg + FL_TILE + so, V16 + gofs);
            }
        }
        CP_COMMIT();
        CP_WAIT1();
        __syncthreads();

        const uint32_t st = sb + (kt & 1) * FL_STAGE;

        float sc[8][4];
#pragma unroll
        for (int ni = 0; ni < 8; ni++)
#pragma unroll
            for (int j = 0; j < 4; j++) sc[ni][j] = 0.f;

#pragma unroll
        for (int ka = 0; ka < 8; ka++) {
#pragma unroll
            for (int nj = 0; nj < 4; nj++) {
                uint32_t ro = (uint32_t)((nj * 16 + b_r) * KSTR + ka * 16 + b_k) * 2;
                uint32_t kk[4];
                ldm_x4(kk, st + ro);
#pragma unroll
                for (int half = 0; half < 2; half++) {
                    const int ni = nj * 2 + half;
                    const int s2 = half * 2;
                    mma16816(sc[ni], qh[ka], kk[s2], kk[s2 + 1]);
                    mma16816(sc[ni], ql[ka], kk[s2], kk[s2 + 1]);
                }
            }
        }

        if (kt == qt) {
            const int row0 = wid * 16 + quad;
#pragma unroll
            for (int ni = 0; ni < 8; ni++) {
                const int c0 = ni * 8 + 2 * tcol;
                if (c0 > row0)     sc[ni][0] = -1e30f;
                if (c0 + 1 > row0) sc[ni][1] = -1e30f;
                if (c0 > row0 + 8)     sc[ni][2] = -1e30f;
                if (c0 + 1 > row0 + 8) sc[ni][3] = -1e30f;
            }
        }

        float mx0 = -1e30f, mx1 = -1e30f;
#pragma unroll
        for (int ni = 0; ni < 8; ni++) {
            mx0 = fmaxf(mx0, fmaxf(sc[ni][0], sc[ni][1]));
            mx1 = fmaxf(mx1, fmaxf(sc[ni][2], sc[ni][3]));
        }
        mx0 = fmaxf(mx0, __shfl_xor_sync(0xffffffffu, mx0, 1));
        mx0 = fmaxf(mx0, __shfl_xor_sync(0xffffffffu, mx0, 2));
        mx1 = fmaxf(mx1, __shfl_xor_sync(0xffffffffu, mx1, 1));
        mx1 = fmaxf(mx1, __shfl_xor_sync(0xffffffffu, mx1, 2));

        const float nm0 = fmaxf(m0, mx0);
        const float nm1 = fmaxf(m1, mx1);
        const float rs0 = __expf(m0 - nm0);
        const float rs1 = __expf(m1 - nm1);
        m0 = nm0; m1 = nm1;

        float ps0 = 0.f, ps1 = 0.f;
#pragma unroll
        for (int ni = 0; ni < 8; ni++) {
            sc[ni][0] = __expf(sc[ni][0] - nm0);
            sc[ni][1] = __expf(sc[ni][1] - nm0);
            sc[ni][2] = __expf(sc[ni][2] - nm1);
            sc[ni][3] = __expf(sc[ni][3] - nm1);
            ps0 += sc[ni][0] + sc[ni][1];
            ps1 += sc[ni][2] + sc[ni][3];
        }
        ps0 += __shfl_xor_sync(0xffffffffu, ps0, 1);
        ps0 += __shfl_xor_sync(0xffffffffu, ps0, 2);
        ps1 += __shfl_xor_sync(0xffffffffu, ps1, 1);
        ps1 += __shfl_xor_sync(0xffffffffu, ps1, 2);
        l0 = l0 * rs0 + ps0;
        l1 = l1 * rs1 + ps1;

#pragma unroll
        for (int g = 0; g < 16; g++) {
            o_acc[g][0] *= rs0; o_acc[g][1] *= rs0;
            o_acc[g][2] *= rs1; o_acc[g][3] *= rs1;
        }

#pragma unroll
        for (int t = 0; t < 4; t++) {
            float p00 = sc[2*t][0],   p01 = sc[2*t][1],   p02 = sc[2*t][2],   p03 = sc[2*t][3];
            float p10 = sc[2*t+1][0], p11 = sc[2*t+1][1], p12 = sc[2*t+1][2], p13 = sc[2*t+1][3];
            uint32_t aph[4], apl[4];
            aph[0] = packh(p00, p01);
            aph[1] = packh(p02, p03);
            aph[2] = packh(p10, p11);
            aph[3] = packh(p12, p13);
            apl[0] = packh(p00 - hround(p00), p01 - hround(p01));
            apl[1] = packh(p02 - hround(p02), p03 - hround(p03));
            apl[2] = packh(p10 - hround(p10), p11 - hround(p11));
            apl[3] = packh(p12 - hround(p12), p13 - hround(p13));

            const uint32_t vbase = st + FL_TILE + (uint32_t)((t * 16 + v_kk) * KSTR + v_d) * 2;
#pragma unroll
            for (int g = 0; g < 8; g++) {
                uint32_t vv[4];
                ldm_x4_t(vv, vbase + (uint32_t)(g * 16) * 2);
                mma16816(o_acc[g*2],   aph, vv[0], vv[1]);
                mma16816(o_acc[g*2+1], aph, vv[2], vv[3]);
                mma16816(o_acc[g*2],   apl, vv[0], vv[1]);
                mma16816(o_acc[g*2+1], apl, vv[2], vv[3]);
            }
        }
        __syncthreads();
    }

    const float inv0 = 1.f / l0;
    const float inv1 = 1.f / l1;
    const int row0 = q0 + wid * 16 + quad;
#pragma unroll
    for (int g = 0; g < 16; g++) {
        const int d = g * 8 + 2 * tcol;
        float a0 = o_acc[g][0] * inv0, a1 = o_acc[g][1] * inv0;
        float a2 = o_acc[g][2] * inv1, a3 = o_acc[g][3] * inv1;
        size_t i0 = (((size_t)b * SEQ + row0) * H_Q + h) * DHEAD + d;
        size_t i1 = (((size_t)b * SEQ + row0 + 8) * H_Q + h) * DHEAD + d;
        *(uint32_t*)&O16[i0] = packh(a0, a1);
        *(uint32_t*)&O16[i1] = packh(a2, a3);
    }
}

// ---------------- launch ----------------
extern "C" void kernel_launch(void* const* d_in, const int* in_sizes, int n_in,
                              void* d_out, int out_size) {
    const float* x  = (const float*)d_in[0];
    const float* wq = (const float*)d_in[1];
    const float* bq = (const float*)d_in[2];
    const float* wk = (const float*)d_in[3];
    const float* bk = (const float*)d_in[4];
    const float* wv = (const float*)d_in[5];
    const float* bv = (const float*)d_in[6];
    const float* wo = (const float*)d_in[7];
    const float* bo = (const float*)d_in[8];
    float* out = (float*)d_out;

    float *ctab, *stab;
    cudaGetSymbolAddress((void**)&ctab, g_cos);
    cudaGetSymbolAddress((void**)&stab, g_sin);

    __half *x16, *wqhi, *wqlo, *wkhi, *wklo, *wvhi, *wvlo, *wohi, *wolo;
    __half *qhi, *qlo, *k16, *v16, *o16;
    cudaGetSymbolAddress((void**)&x16, g_x16);
    cudaGetSymbolAddress((void**)&wqhi, g_wqhi); cudaGetSymbolAddress((void**)&wqlo, g_wqlo);
    cudaGetSymbolAddress((void**)&wkhi, g_wkhi); cudaGetSymbolAddress((void**)&wklo, g_wklo);
    cudaGetSymbolAddress((void**)&wvhi, g_wvhi); cudaGetSymbolAddress((void**)&wvlo, g_wvlo);
    cudaGetSymbolAddress((void**)&wohi, g_wohi); cudaGetSymbolAddress((void**)&wolo, g_wolo);
    cudaGetSymbolAddress((void**)&qhi, g_qhi);   cudaGetSymbolAddress((void**)&qlo, g_qlo);
    cudaGetSymbolAddress((void**)&k16, g_k16);   cudaGetSymbolAddress((void**)&v16, g_v16);
    cudaGetSymbolAddress((void**)&o16, g_o16);

    const int M = BATCH * SEQ;   // 8192

    cudaFuncSetAttribute(gemm_mma_bias, cudaFuncAttributeMaxDynamicSharedMemorySize, GEMM_SMEM);
    cudaFuncSetAttribute(flash_mma_kernel, cudaFuncAttributeMaxDynamicSharedMemorySize, FL_SMEM);

    rope_table_kernel<<<(SEQ * 64 + 255) / 256, 256>>>(ctab, stab);
    cvt_f16_kernel<<<(XN / 4 + 255) / 256, 256>>>(x, x16, XN / 4);
    split_f16_kernel<<<(WQN / 4 + 255) / 256, 256>>>(wq, wqhi, wqlo, WQN / 4);
    split_f16_kernel<<<(WKN / 4 + 255) / 256, 256>>>(wk, wkhi, wklo, WKN / 4);
    split_f16_kernel<<<(WKN / 4 + 255) / 256, 256>>>(wv, wvhi, wvlo, WKN / 4);
    split_f16_kernel<<<(WQN / 4 + 255) / 256, 256>>>(wo, wohi, wolo, WQN / 4);

    // projections (128x128 tiles, 2 CTAs/SM)
    gemm_mma_bias<<<dim3(EMB / 128, M / 128), 256, GEMM_SMEM>>>(
        x16, wqhi, wqlo, bq, (float*)0, (__half*)0, qhi, qlo, 2, M, EMB, EMB);
    gemm_mma_bias<<<dim3(KVDIM / 128, M / 128), 256, GEMM_SMEM>>>(
        x16, wkhi, wklo, bk, (float*)0, k16, (__half*)0, (__half*)0, 1, M, KVDIM, EMB);
    gemm_mma_bias<<<dim3(KVDIM / 128, M / 128), 256, GEMM_SMEM>>>(
        x16, wvhi, wvlo, bv, (float*)0, v16, (__half*)0, (__half*)0, 1, M, KVDIM, EMB);

    // RoPE
    {
        const float qscale = 0.08838834764831845f;   // 1/sqrt(128)
        int tq = BATCH * SEQ * H_Q * 64;
        rope_hl_kernel<<<(tq + 255) / 256, 256>>>(qhi, qlo, ctab, stab, H_Q, qscale);
        int tk = BATCH * SEQ * H_KV * 64;
        rope_s_kernel<<<(tk + 255) / 256, 256>>>(k16, ctab, stab, H_KV);
    }

    // flash attention -> o16
    flash_mma_kernel<<<dim3(SEQ / 64, BATCH * H_Q), 128, FL_SMEM>>>(
        qhi, qlo, k16, v16, o16);

    // output projection (fp32 out)
    gemm_mma_bias<<<dim3(EMB / 128, M / 128), 256, GEMM_SMEM>>>(
        o16, wohi, wolo, bo, out, (__half*)0, (__half*)0, (__half*)0, 0, M, EMB, EMB);
}

// round 17
// speedup vs baseline: 1.0258x; 1.0199x over previous
#include <cuda_runtime.h>
#include <cuda_fp16.h>
#include <math.h>
#include <stdint.h>

#define BATCH 4
#define SEQ   2048
#define EMB   2048
#define H_Q   16
#define H_KV  4
#define DHEAD 128
#define KVDIM (H_KV*DHEAD)     // 512
#define GQA   (H_Q/H_KV)       // 4

#define XN   (BATCH*SEQ*EMB)
#define KN   (BATCH*SEQ*KVDIM)
#define WQN  (EMB*EMB)
#define WKN  (KVDIM*EMB)
#define NQKV (EMB + 2*KVDIM)   // 3072

// ---------------- scratch (no allocations allowed) ----------------
__device__ float g_cos[SEQ*64];
__device__ float g_sin[SEQ*64];
__device__ __half g_x16[XN];
__device__ __half g_wqkvhi[NQKV*EMB], g_wqkvlo[NQKV*EMB];   // [3072,2048] combined
__device__ __half g_wohi[WQN], g_wolo[WQN];
__device__ __half g_qhi[XN], g_qlo[XN];
__device__ __half g_k16[KN], g_v16[KN];
__device__ __half g_o16[XN];

// ---------------- helpers ----------------
__device__ __forceinline__ uint32_t smem_u32(const void* p) {
    uint32_t a;
    asm("{ .reg .u64 t; cvta.to.shared.u64 t, %1; cvt.u32.u64 %0, t; }" : "=r"(a) : "l"(p));
    return a;
}
__device__ __forceinline__ void cp16(uint32_t dst, const void* src) {
    asm volatile("cp.async.cg.shared.global [%0], [%1], 16;" :: "r"(dst), "l"(src) : "memory");
}
#define CP_COMMIT() asm volatile("cp.async.commit_group;" ::: "memory")
#define CP_WAIT0()  asm volatile("cp.async.wait_group 0;" ::: "memory")
#define CP_WAIT1()  asm volatile("cp.async.wait_group 1;" ::: "memory")

__device__ __forceinline__ void ldm_x4(uint32_t* r, uint32_t addr) {
    asm volatile("ldmatrix.sync.aligned.m8n8.x4.shared.b16 {%0,%1,%2,%3}, [%4];"
                 : "=r"(r[0]), "=r"(r[1]), "=r"(r[2]), "=r"(r[3]) : "r"(addr));
}
__device__ __forceinline__ void ldm_x4_t(uint32_t* r, uint32_t addr) {
    asm volatile("ldmatrix.sync.aligned.m8n8.x4.trans.shared.b16 {%0,%1,%2,%3}, [%4];"
                 : "=r"(r[0]), "=r"(r[1]), "=r"(r[2]), "=r"(r[3]) : "r"(addr));
}
__device__ __forceinline__ void mma16816(float* c, const uint32_t* a, uint32_t b0, uint32_t b1) {
    asm volatile(
        "mma.sync.aligned.m16n8k16.row.col.f32.f16.f16.f32 "
        "{%0,%1,%2,%3}, {%4,%5,%6,%7}, {%8,%9}, {%0,%1,%2,%3};"
        : "+f"(c[0]), "+f"(c[1]), "+f"(c[2]), "+f"(c[3])
        : "r"(a[0]), "r"(a[1]), "r"(a[2]), "r"(a[3]), "r"(b0), "r"(b1));
}
__device__ __forceinline__ uint32_t packh(float lo, float hi) {
    uint32_t r;
    asm("cvt.rn.f16x2.f32 %0, %1, %2;" : "=r"(r) : "f"(hi), "f"(lo));
    return r;
}
__device__ __forceinline__ float hround(float x) {
    return __half2float(__float2half(x));
}

// ---------------- fp32 -> fp16 convert (single) ----------------
__global__ void cvt_f16_kernel(const float* __restrict__ src, __half* __restrict__ dst, int n4) {
    int i = blockIdx.x * blockDim.x + threadIdx.x;
    if (i >= n4) return;
    float4 v = ((const float4*)src)[i];
    uint2 o;
    o.x = packh(v.x, v.y);
    o.y = packh(v.z, v.w);
    ((uint2*)dst)[i] = o;
}

// ---------------- fp32 -> fp16 hi/lo split ----------------
__global__ void split_f16_kernel(const float* __restrict__ src,
                                 __half* __restrict__ hi, __half* __restrict__ lo, int n4) {
    int i = blockIdx.x * blockDim.x + threadIdx.x;
    if (i >= n4) return;
    float4 v = ((const float4*)src)[i];
    float h0 = hround(v.x), h1 = hround(v.y), h2 = hround(v.z), h3 = hround(v.w);
    uint2 hv, lv;
    hv.x = packh(h0, h1);
    hv.y = packh(h2, h3);
    lv.x = packh(v.x - h0, v.y - h1);
    lv.y = packh(v.z - h2, v.w - h3);
    ((uint2*)hi)[i] = hv;
    ((uint2*)lo)[i] = lv;
}

// ---------------- RoPE table ----------------
__global__ void rope_table_kernel(float* ctab, float* stab) {
    int idx = blockIdx.x * blockDim.x + threadIdx.x;
    if (idx >= SEQ * 64) return;
    int pos = idx >> 6;
    int j   = idx & 63;
    float invf = expf(-(float)j * (9.210340371976184f / 64.0f));
    float arg = (float)pos * invf;
    float s, c;
    sincosf(arg, &s, &c);
    ctab[idx] = c;
    stab[idx] = s;
}

// ---------------- in-place RoPE on fp16 hi/lo pairs ----------------
__global__ void rope_hl_kernel(__half* __restrict__ hi, __half* __restrict__ lo,
                               const float* __restrict__ ctab, const float* __restrict__ stab,
                               int nheads, float scale) {
    int idx = blockIdx.x * blockDim.x + threadIdx.x;
    int total = BATCH * SEQ * nheads * 64;
    if (idx >= total) return;
    int j  = idx & 63;
    int tt = idx >> 6;
    int h  = tt % nheads;
    int t2 = tt / nheads;
    int s  = t2 % SEQ;
    int b  = t2 / SEQ;
    float c  = ctab[s * 64 + j];
    float sn = stab[s * 64 + j];
    size_t base = (((size_t)b * SEQ + s) * nheads + h) * DHEAD;
    float x0 = __half2float(hi[base + j])      + __half2float(lo[base + j]);
    float x1 = __half2float(hi[base + 64 + j]) + __half2float(lo[base + 64 + j]);
    float y0 = (x0 * c - x1 * sn) * scale;
    float y1 = (x1 * c + x0 * sn) * scale;
    float h0 = hround(y0), h1 = hround(y1);
    hi[base + j]      = __float2half(y0);
    hi[base + 64 + j] = __float2half(y1);
    lo[base + j]      = __float2half(y0 - h0);
    lo[base + 64 + j] = __float2half(y1 - h1);
}

// ---------------- in-place RoPE on single fp16 ----------------
__global__ void rope_s_kernel(__half* __restrict__ t,
                              const float* __restrict__ ctab, const float* __restrict__ stab,
                              int nheads) {
    int idx = blockIdx.x * blockDim.x + threadIdx.x;
    int total = BATCH * SEQ * nheads * 64;
    if (idx >= total) return;
    int j  = idx & 63;
    int tt = idx >> 6;
    int h  = tt % nheads;
    int t2 = tt / nheads;
    int s  = t2 % SEQ;
    int b  = t2 / SEQ;
    float c  = ctab[s * 64 + j];
    float sn = stab[s * 64 + j];
    size_t base = (((size_t)b * SEQ + s) * nheads + h) * DHEAD;
    float x0 = __half2float(t[base + j]);
    float x1 = __half2float(t[base + 64 + j]);
    t[base + j]      = __float2half(x0 * c - x1 * sn);
    t[base + 64 + j] = __float2half(x1 * c + x0 * sn);
}

// ---------------- warp-MMA GEMM: C = A @ B^T + bias (fp16 2-pass, BK=64) ----------------
// A: single fp16 [M,K]; B: fp16 hi/lo [N,K]. 128x128 tile, BK=64, 8 warps (2m x 4n).
// mode 0: C fp32 (bias=bias0)
// mode 3: fused QKV epilogue — bn<2048 -> Qhi/Qlo split (bias0); bn<2560 -> Kh (bias1);
//         else -> Vh (bias2). N param is the combined width (3072).
#define TSTRIDE 72
#define TILE_B  (128 * TSTRIDE * 2)      // 18432
#define STAGE_B (3 * TILE_B)             // 55296
#define GEMM_SMEM (2 * STAGE_B)          // 110592

__global__ __launch_bounds__(256, 2)
void gemm_mma_bias(const __half* __restrict__ A16,
                   const __half* __restrict__ Bhi, const __half* __restrict__ Blo,
                   const float* __restrict__ bias0, const float* __restrict__ bias1,
                   const float* __restrict__ bias2,
                   float* __restrict__ C,
                   __half* __restrict__ Qhi, __half* __restrict__ Qlo,
                   __half* __restrict__ Kh, __half* __restrict__ Vh,
                   int mode, int M, int N, int K) {
    extern __shared__ char dsm[];
    const uint32_t sbase = smem_u32(dsm);

    const int tid  = threadIdx.x;
    const int wid  = tid >> 5;
    const int lane = tid & 31;

    const int bm = blockIdx.y * 128;
    const int bn = blockIdx.x * 128;
    const int warp_m = (wid & 1) * 64;     // 2 m-warps of 64 rows
    const int warp_n = (wid >> 1) * 32;    // 4 n-warps of 32 cols

    const __half* srcs[3] = {A16, Bhi, Blo};
    const int rowbase[3] = {bm, bn, bn};

    const int a_r = lane & 15;
    const int a_k = (lane >> 4) * 8;
    const int b_r = ((lane >> 4) << 3) + (lane & 7);
    const int b_k = ((lane >> 3) & 1) * 8;

    float acc[4][4][4];
#pragma unroll
    for (int mi = 0; mi < 4; mi++)
#pragma unroll
        for (int ni = 0; ni < 4; ni++)
#pragma unroll
            for (int j = 0; j < 4; j++) acc[mi][ni][j] = 0.f;

    const int NC = K >> 6;   // 64-wide chunks

#pragma unroll
    for (int t = 0; t < 3; t++) {
#pragma unroll
        for (int s = 0; s < 4; s++) {
            int seg = tid + s * 256;          // 0..1023
            int row = seg >> 3;
            int qq  = seg & 7;
            const __half* g = srcs[t] + (size_t)(rowbase[t] + row) * K + qq * 8;
            cp16(sbase + t * TILE_B + (uint32_t)(row * TSTRIDE + qq * 8) * 2, g);
        }
    }
    CP_COMMIT();

    for (int c = 0; c < NC; c++) {
        CP_WAIT0();
        __syncthreads();

        if (c + 1 < NC) {
            const uint32_t stg = sbase + ((c + 1) & 1) * STAGE_B;
            const int kt = (c + 1) << 6;
#pragma unroll
            for (int t = 0; t < 3; t++) {
#pragma unroll
                for (int s = 0; s < 4; s++) {
                    int seg = tid + s * 256;
                    int row = seg >> 3;
                    int qq  = seg & 7;
                    const __half* g = srcs[t] + (size_t)(rowbase[t] + row) * K + kt + qq * 8;
                    cp16(stg + t * TILE_B + (uint32_t)(row * TSTRIDE + qq * 8) * 2, g);
                }
            }
            CP_COMMIT();
        }

        const uint32_t stage = sbase + (c & 1) * STAGE_B;
#pragma unroll
        for (int ka = 0; ka < 64; ka += 16) {
            uint32_t ah[4][4];
#pragma unroll
            for (int mi = 0; mi < 4; mi++) {
                uint32_t ro = (uint32_t)((warp_m + mi * 16 + a_r) * TSTRIDE + ka + a_k) * 2;
                ldm_x4(ah[mi], stage + 0 * TILE_B + ro);
            }
#pragma unroll
            for (int nj = 0; nj < 2; nj++) {
                uint32_t ro = (uint32_t)((warp_n + nj * 16 + b_r) * TSTRIDE + ka + b_k) * 2;
                uint32_t bh[4], bl[4];
                ldm_x4(bh, stage + 1 * TILE_B + ro);
                ldm_x4(bl, stage + 2 * TILE_B + ro);
#pragma unroll
                for (int mi = 0; mi < 4; mi++)
#pragma unroll
                    for (int half = 0; half < 2; half++) {
                        const int ni = nj * 2 + half;
                        const int s  = half * 2;
                        mma16816(acc[mi][ni], ah[mi], bh[s], bh[s + 1]);
                        mma16816(acc[mi][ni], ah[mi], bl[s], bl[s + 1]);
                    }
            }
        }
        __syncthreads();
    }

    const int quad = lane >> 2;
    const int tcol = lane & 3;

    if (mode == 0) {
#pragma unroll
        for (int mi = 0; mi < 4; mi++)
#pragma unroll
            for (int ni = 0; ni < 4; ni++) {
                const int m0 = bm + warp_m + mi * 16 + quad;
                const int n0 = bn + warp_n + ni * 8 + tcol * 2;
                const float b0 = bias0[n0], b1 = bias0[n0 + 1];
                float c00 = acc[mi][ni][0] + b0, c01 = acc[mi][ni][1] + b1;
                float c10 = acc[mi][ni][2] + b0, c11 = acc[mi][ni][3] + b1;
                *(float2*)&C[(size_t)m0 * N + n0]       = make_float2(c00, c01);
                *(float2*)&C[(size_t)(m0 + 8) * N + n0] = make_float2(c10, c11);
            }
    } else {
        // fused QKV routing: uniform per CTA column block
        if (bn < EMB) {
            // Q: hi/lo split, width EMB
#pragma unroll
            for (int mi = 0; mi < 4; mi++)
#pragma unroll
                for (int ni = 0; ni < 4; ni++) {
                    const int m0 = bm + warp_m + mi * 16 + quad;
                    const int n0 = bn + warp_n + ni * 8 + tcol * 2;
                    const float b0 = bias0[n0], b1 = bias0[n0 + 1];
                    float c00 = acc[mi][ni][0] + b0, c01 = acc[mi][ni][1] + b1;
                    float c10 = acc[mi][ni][2] + b0, c11 = acc[mi][ni][3] + b1;
                    size_t i0 = (size_t)m0 * EMB + n0;
                    size_t i1 = (size_t)(m0 + 8) * EMB + n0;
                    *(uint32_t*)&Qhi[i0] = packh(c00, c01);
                    *(uint32_t*)&Qhi[i1] = packh(c10, c11);
                    *(uint32_t*)&Qlo[i0] = packh(c00 - hround(c00), c01 - hround(c01));
                    *(uint32_t*)&Qlo[i1] = packh(c10 - hround(c10), c11 - hround(c11));
                }
        } else {
            const bool isK = (bn < EMB + KVDIM);
            __half* dst = isK ? Kh : Vh;
            const float* bi = isK ? bias1 : bias2;
            const int coff = isK ? EMB : (EMB + KVDIM);
#pragma unroll
            for (int mi = 0; mi < 4; mi++)
#pragma unroll
                for (int ni = 0; ni < 4; ni++) {
                    const int m0 = bm + warp_m + mi * 16 + quad;
                    const int n0 = bn + warp_n + ni * 8 + tcol * 2 - coff;
                    const float b0 = bi[n0], b1 = bi[n0 + 1];
                    float c00 = acc[mi][ni][0] + b0, c01 = acc[mi][ni][1] + b1;
                    float c10 = acc[mi][ni][2] + b0, c11 = acc[mi][ni][3] + b1;
                    size_t i0 = (size_t)m0 * KVDIM + n0;
                    size_t i1 = (size_t)(m0 + 8) * KVDIM + n0;
                    *(uint32_t*)&dst[i0] = packh(c00, c01);
                    *(uint32_t*)&dst[i1] = packh(c10, c11);
                }
        }
    }
}

// ---------------- tensor-core flash attention (fp16 2-pass, double-buffered K/V) ----------------
#define KSTR 136
#define FL_TILE  (64 * KSTR * 2)     // 17408
#define FL_STAGE (2 * FL_TILE)       // 34816
#define FL_SMEM  (2 * FL_STAGE)      // 69632

__global__ __launch_bounds__(128, 2)
void flash_mma_kernel(const __half* __restrict__ Qhi, const __half* __restrict__ Qlo,
                      const __half* __restrict__ K16, const __half* __restrict__ V16,
                      __half* __restrict__ O16) {
    extern __shared__ char sm2[];
    const uint32_t sb = smem_u32(sm2);

    const int qt  = gridDim.x - 1 - blockIdx.x;
    const int bh  = blockIdx.y;
    const int b   = bh >> 4;
    const int h   = bh & 15;
    const int kvh = h >> 2;
    const int q0  = qt * 64;
    const int tid = threadIdx.x;
    const int wid = tid >> 5;
    const int lane = tid & 31;
    const int quad = lane >> 2;
    const int tcol = lane & 3;

#pragma unroll
    for (int s = 0; s < 8; s++) {
        int seg = tid + s * 128;
        int r   = seg >> 4;
        int cg  = seg & 15;
        size_t gofs = (((size_t)b * SEQ + q0 + r) * H_Q + h) * DHEAD + cg * 8;
        uint32_t so = (uint32_t)(r * KSTR + cg * 8) * 2;
        cp16(sb + so, Qhi + gofs);
        cp16(sb + FL_TILE + so, Qlo + gofs);
    }
    CP_COMMIT();
    CP_WAIT0();
    __syncthreads();

    uint32_t qh[8][4], ql[8][4];
    {
        const int a_r = lane & 15;
        const int a_k = (lane >> 4) * 8;
#pragma unroll
        for (int ka = 0; ka < 8; ka++) {
            uint32_t ro = (uint32_t)((wid * 16 + a_r) * KSTR + ka * 16 + a_k) * 2;
            ldm_x4(qh[ka], sb + ro);
            ldm_x4(ql[ka], sb + FL_TILE + ro);
        }
    }
    __syncthreads();

    float o_acc[16][4];
#pragma unroll
    for (int g = 0; g < 16; g++)
#pragma unroll
        for (int j = 0; j < 4; j++) o_acc[g][j] = 0.f;

    float m0 = -1e30f, m1 = -1e30f, l0 = 0.f, l1 = 0.f;

    const int b_r = ((lane >> 4) << 3) + (lane & 7);
    const int b_k = ((lane >> 3) & 1) * 8;
    const int v_kk = (lane & 7) + ((lane >> 3) & 1) * 8;
    const int v_d  = ((lane >> 4) & 1) * 8;

#pragma unroll
    for (int s = 0; s < 8; s++) {
        int seg = tid + s * 128;
        int r   = seg >> 4;
        int cg  = seg & 15;
        size_t gofs = (((size_t)b * SEQ + r) * H_KV + kvh) * DHEAD + cg * 8;
        uint32_t so = (uint32_t)(r * KSTR + cg * 8) * 2;
        cp16(sb + so, K16 + gofs);
        cp16(sb + FL_TILE + so, V16 + gofs);
    }
    CP_COMMIT();

    for (int kt = 0; kt <= qt; kt++) {
        if (kt + 1 <= qt) {
            const uint32_t stg = sb + ((kt + 1) & 1) * FL_STAGE;
            const int k0n = (kt + 1) * 64;
#pragma unroll
            for (int s = 0; s < 8; s++) {
                int seg = tid + s * 128;
                int r   = seg >> 4;
                int cg  = seg & 15;
                size_t gofs = (((size_t)b * SEQ + k0n + r) * H_KV + kvh) * DHEAD + cg * 8;
                uint32_t so = (uint32_t)(r * KSTR + cg * 8) * 2;
                cp16(stg + so, K16 + gofs);
                cp16(stg + FL_TILE + so, V16 + gofs);
            }
        }
        CP_COMMIT();
        CP_WAIT1();
        __syncthreads();

        const uint32_t st = sb + (kt & 1) * FL_STAGE;

        float sc[8][4];
#pragma unroll
        for (int ni = 0; ni < 8; ni++)
#pragma unroll
            for (int j = 0; j < 4; j++) sc[ni][j] = 0.f;

#pragma unroll
        for (int ka = 0; ka < 8; ka++) {
#pragma unroll
            for (int nj = 0; nj < 4; nj++) {
                uint32_t ro = (uint32_t)((nj * 16 + b_r) * KSTR + ka * 16 + b_k) * 2;
                uint32_t kk[4];
                ldm_x4(kk, st + ro);
#pragma unroll
                for (int half = 0; half < 2; half++) {
                    const int ni = nj * 2 + half;
                    const int s2 = half * 2;
                    mma16816(sc[ni], qh[ka], kk[s2], kk[s2 + 1]);
                    mma16816(sc[ni], ql[ka], kk[s2], kk[s2 + 1]);
                }
            }
        }

        if (kt == qt) {
            const int row0 = wid * 16 + quad;
#pragma unroll
            for (int ni = 0; ni < 8; ni++) {
                const int c0 = ni * 8 + 2 * tcol;
                if (c0 > row0)     sc[ni][0] = -1e30f;
                if (c0 + 1 > row0) sc[ni][1] = -1e30f;
                if (c0 > row0 + 8)     sc[ni][2] = -1e30f;
                if (c0 + 1 > row0 + 8) sc[ni][3] = -1e30f;
            }
        }

        float mx0 = -1e30f, mx1 = -1e30f;
#pragma unroll
        for (int ni = 0; ni < 8; ni++) {
            mx0 = fmaxf(mx0, fmaxf(sc[ni][0], sc[ni][1]));
            mx1 = fmaxf(mx1, fmaxf(sc[ni][2], sc[ni][3]));
        }
        mx0 = fmaxf(mx0, __shfl_xor_sync(0xffffffffu, mx0, 1));
        mx0 = fmaxf(mx0, __shfl_xor_sync(0xffffffffu, mx0, 2));
        mx1 = fmaxf(mx1, __shfl_xor_sync(0xffffffffu, mx1, 1));
        mx1 = fmaxf(mx1, __shfl_xor_sync(0xffffffffu, mx1, 2));

        const float nm0 = fmaxf(m0, mx0);
        const float nm1 = fmaxf(m1, mx1);
        const float rs0 = __expf(m0 - nm0);
        const float rs1 = __expf(m1 - nm1);
        m0 = nm0; m1 = nm1;

        float ps0 = 0.f, ps1 = 0.f;
#pragma unroll
        for (int ni = 0; ni < 8; ni++) {
            sc[ni][0] = __expf(sc[ni][0] - nm0);
            sc[ni][1] = __expf(sc[ni][1] - nm0);
            sc[ni][2] = __expf(sc[ni][2] - nm1);
            sc[ni][3] = __expf(sc[ni][3] - nm1);
            ps0 += sc[ni][0] + sc[ni][1];
            ps1 += sc[ni][2] + sc[ni][3];
        }
        ps0 += __shfl_xor_sync(0xffffffffu, ps0, 1);
        ps0 += __shfl_xor_sync(0xffffffffu, ps0, 2);
        ps1 += __shfl_xor_sync(0xffffffffu, ps1, 1);
        ps1 += __shfl_xor_sync(0xffffffffu, ps1, 2);
        l0 = l0 * rs0 + ps0;
        l1 = l1 * rs1 + ps1;

#pragma unroll
        for (int g = 0; g < 16; g++) {
            o_acc[g][0] *= rs0; o_acc[g][1] *= rs0;
            o_acc[g][2] *= rs1; o_acc[g][3] *= rs1;
        }

#pragma unroll
        for (int t = 0; t < 4; t++) {
            float p00 = sc[2*t][0],   p01 = sc[2*t][1],   p02 = sc[2*t][2],   p03 = sc[2*t][3];
            float p10 = sc[2*t+1][0], p11 = sc[2*t+1][1], p12 = sc[2*t+1][2], p13 = sc[2*t+1][3];
            uint32_t aph[4], apl[4];
            aph[0] = packh(p00, p01);
            aph[1] = packh(p02, p03);
            aph[2] = packh(p10, p11);
            aph[3] = packh(p12, p13);
            apl[0] = packh(p00 - hround(p00), p01 - hround(p01));
            apl[1] = packh(p02 - hround(p02), p03 - hround(p03));
            apl[2] = packh(p10 - hround(p10), p11 - hround(p11));
            apl[3] = packh(p12 - hround(p12), p13 - hround(p13));

            const uint32_t vbase = st + FL_TILE + (uint32_t)((t * 16 + v_kk) * KSTR + v_d) * 2;
#pragma unroll
            for (int g = 0; g < 8; g++) {
                uint32_t vv[4];
                ldm_x4_t(vv, vbase + (uint32_t)(g * 16) * 2);
                mma16816(o_acc[g*2],   aph, vv[0], vv[1]);
                mma16816(o_acc[g*2+1], aph, vv[2], vv[3]);
                mma16816(o_acc[g*2],   apl, vv[0], vv[1]);
                mma16816(o_acc[g*2+1], apl, vv[2], vv[3]);
            }
        }
        __syncthreads();
    }

    const float inv0 = 1.f / l0;
    const float inv1 = 1.f / l1;
    const int row0 = q0 + wid * 16 + quad;
#pragma unroll
    for (int g = 0; g < 16; g++) {
        const int d = g * 8 + 2 * tcol;
        float a0 = o_acc[g][0] * inv0, a1 = o_acc[g][1] * inv0;
        float a2 = o_acc[g][2] * inv1, a3 = o_acc[g][3] * inv1;
        size_t i0 = (((size_t)b * SEQ + row0) * H_Q + h) * DHEAD + d;
        size_t i1 = (((size_t)b * SEQ + row0 + 8) * H_Q + h) * DHEAD + d;
        *(uint32_t*)&O16[i0] = packh(a0, a1);
        *(uint32_t*)&O16[i1] = packh(a2, a3);
    }
}

// ---------------- launch ----------------
extern "C" void kernel_launch(void* const* d_in, const int* in_sizes, int n_in,
                              void* d_out, int out_size) {
    const float* x  = (const float*)d_in[0];
    const float* wq = (const float*)d_in[1];
    const float* bq = (const float*)d_in[2];
    const float* wk = (const float*)d_in[3];
    const float* bk = (const float*)d_in[4];
    const float* wv = (const float*)d_in[5];
    const float* bv = (const float*)d_in[6];
    const float* wo = (const float*)d_in[7];
    const float* bo = (const float*)d_in[8];
    float* out = (float*)d_out;

    float *ctab, *stab;
    cudaGetSymbolAddress((void**)&ctab, g_cos);
    cudaGetSymbolAddress((void**)&stab, g_sin);

    __half *x16, *wqkvhi, *wqkvlo, *wohi, *wolo;
    __half *qhi, *qlo, *k16, *v16, *o16;
    cudaGetSymbolAddress((void**)&x16, g_x16);
    cudaGetSymbolAddress((void**)&wqkvhi, g_wqkvhi);
    cudaGetSymbolAddress((void**)&wqkvlo, g_wqkvlo);
    cudaGetSymbolAddress((void**)&wohi, g_wohi); cudaGetSymbolAddress((void**)&wolo, g_wolo);
    cudaGetSymbolAddress((void**)&qhi, g_qhi);   cudaGetSymbolAddress((void**)&qlo, g_qlo);
    cudaGetSymbolAddress((void**)&k16, g_k16);   cudaGetSymbolAddress((void**)&v16, g_v16);
    cudaGetSymbolAddress((void**)&o16, g_o16);

    const int M = BATCH * SEQ;   // 8192

    cudaFuncSetAttribute(gemm_mma_bias, cudaFuncAttributeMaxDynamicSharedMemorySize, GEMM_SMEM);
    cudaFuncSetAttribute(flash_mma_kernel, cudaFuncAttributeMaxDynamicSharedMemorySize, FL_SMEM);

    rope_table_kernel<<<(SEQ * 64 + 255) / 256, 256>>>(ctab, stab);
    cvt_f16_kernel<<<(XN / 4 + 255) / 256, 256>>>(x, x16, XN / 4);
    // weight splits into combined [3072,2048] layout: wq rows 0..2047, wk 2048..2559, wv 2560..3071
    split_f16_kernel<<<(WQN / 4 + 255) / 256, 256>>>(wq, wqkvhi, wqkvlo, WQN / 4);
    split_f16_kernel<<<(WKN / 4 + 255) / 256, 256>>>(wk, wqkvhi + (size_t)EMB * EMB,
                                                     wqkvlo + (size_t)EMB * EMB, WKN / 4);
    split_f16_kernel<<<(WKN / 4 + 255) / 256, 256>>>(wv, wqkvhi + (size_t)(EMB + KVDIM) * EMB,
                                                     wqkvlo + (size_t)(EMB + KVDIM) * EMB, WKN / 4);
    split_f16_kernel<<<(WQN / 4 + 255) / 256, 256>>>(wo, wohi, wolo, WQN / 4);

    // fused QKV projection: one launch, N=3072
    gemm_mma_bias<<<dim3(NQKV / 128, M / 128), 256, GEMM_SMEM>>>(
        x16, wqkvhi, wqkvlo, bq, bk, bv,
        (float*)0, qhi, qlo, k16, v16, 3, M, NQKV, EMB);

    // RoPE
    {
        const float qscale = 0.08838834764831845f;   // 1/sqrt(128)
        int tq = BATCH * SEQ * H_Q * 64;
        rope_hl_kernel<<<(tq + 255) / 256, 256>>>(qhi, qlo, ctab, stab, H_Q, qscale);
        int tk = BATCH * SEQ * H_KV * 64;
        rope_s_kernel<<<(tk + 255) / 256, 256>>>(k16, ctab, stab, H_KV);
    }

    // flash attention -> o16
    flash_mma_kernel<<<dim3(SEQ / 64, BATCH * H_Q), 128, FL_SMEM>>>(
        qhi, qlo, k16, v16, o16);

    // output projection (fp32 out)
    gemm_mma_bias<<<dim3(EMB / 128, M / 128), 256, GEMM_SMEM>>>(
        o16, wohi, wolo, bo, (float*)0, (float*)0,
        out, (__half*)0, (__half*)0, (__half*)0, (__half*)0, 0, M, EMB, EMB);
}